// round 1
// baseline (speedup 1.0000x reference)
#include <cuda_runtime.h>
#include <math.h>

#define BB 64
#define NNODE 500
#define DIMS 40
#define BN_SCALE 0.99999500003749968750f  // 1/sqrt(1+1e-5)

// ---------------- scratch (device globals; no allocation allowed) ----------------
__device__ float g_adp [BB * NNODE * NNODE];   // 64 MB
__device__ float g_adp2[BB * NNODE * NNODE];   // 64 MB
__device__ float g_T1[BB * DIMS * DIMS];
__device__ float g_T2[BB * DIMS * DIMS];
__device__ float g_M1[BB * NNODE * DIMS];
__device__ float g_M2[BB * NNODE * DIMS];
__device__ float g_S0 [BB * NNODE * 512];
__device__ float g_S1 [BB * NNODE * 512];
__device__ float g_G  [BB * NNODE * 512];
__device__ float g_Y1 [BB * NNODE * 512];
__device__ float g_Y2 [BB * NNODE * 512];
__device__ float g_G01[BB * NNODE * 512];
__device__ float g_Z1 [BB * NNODE * 256];
__device__ float g_Z2 [BB * NNODE * 256];
__device__ float g_SK [BB * NNODE * 304];

// ---------------- graph construction ----------------
// T[b,j,k] = sum_i p1[ind[b],i] * pk[i,j,k]
__global__ void k_T(const float* __restrict__ p1, const float* __restrict__ pk,
                    const int* __restrict__ ind, float* __restrict__ Tout) {
    int b = blockIdx.x;
    __shared__ float te[DIMS];
    int day = ind[b];
    if (threadIdx.x < DIMS) te[threadIdx.x] = p1[day * DIMS + threadIdx.x];
    __syncthreads();
    for (int jk = threadIdx.x; jk < DIMS * DIMS; jk += blockDim.x) {
        float s = 0.f;
#pragma unroll
        for (int i = 0; i < DIMS; i++) s += te[i] * pk[i * DIMS * DIMS + jk];
        Tout[b * DIMS * DIMS + jk] = s;
    }
}

// M[b,w,k] = sum_j p2[w,j] * T[b,j,k]
__global__ void k_M(const float* __restrict__ p2, const float* __restrict__ T,
                    float* __restrict__ M) {
    int idx = blockIdx.x * blockDim.x + threadIdx.x;
    if (idx >= BB * NNODE * DIMS) return;
    int k = idx % DIMS;
    int w = (idx / DIMS) % NNODE;
    int b = idx / (DIMS * NNODE);
    float s = 0.f;
    const float* Tb = T + b * DIMS * DIMS;
#pragma unroll
    for (int j = 0; j < DIMS; j++) s += p2[w * DIMS + j] * Tb[j * DIMS + k];
    M[idx] = s;
}

// A[b,w,v] = softmax_v( relu( sum_k p3[v,k] * M[b,w,k] ) )
__global__ void k_adp(const float* __restrict__ M, const float* __restrict__ p3,
                      float* __restrict__ A) {
    int bw = blockIdx.x;                  // b*NNODE + w
    __shared__ float mrow[DIMS];
    __shared__ float vals[NNODE];
    __shared__ float red[256];
    int tid = threadIdx.x;
    if (tid < DIMS) mrow[tid] = M[(size_t)bw * DIMS + tid];
    __syncthreads();
    for (int v = tid; v < NNODE; v += 256) {
        float s = 0.f;
#pragma unroll
        for (int k = 0; k < DIMS; k++) s += p3[v * DIMS + k] * mrow[k];
        vals[v] = fmaxf(s, 0.f);
    }
    __syncthreads();
    float m = 0.f;
    for (int v = tid; v < NNODE; v += 256) m = fmaxf(m, vals[v]);
    red[tid] = m; __syncthreads();
    for (int s2 = 128; s2 > 0; s2 >>= 1) {
        if (tid < s2) red[tid] = fmaxf(red[tid], red[tid + s2]);
        __syncthreads();
    }
    m = red[0];
    __syncthreads();
    float sum = 0.f;
    for (int v = tid; v < NNODE; v += 256) {
        float e = expf(vals[v] - m);
        vals[v] = e; sum += e;
    }
    red[tid] = sum; __syncthreads();
    for (int s2 = 128; s2 > 0; s2 >>= 1) {
        if (tid < s2) red[tid] += red[tid + s2];
        __syncthreads();
    }
    float inv = 1.f / red[0];
    float* Ar = A + (size_t)bw * NNODE;
    for (int v = tid; v < NNODE; v += 256) Ar[v] = vals[v] * inv;
}

// ---------------- start embedding ----------------
// S[bn][(s*16+c)*16 + t] = inputs[b,t,n,s] * sw[s*16+c] + sb[s*16+c]
__global__ void k_start(const float* __restrict__ inp, const float* __restrict__ sw,
                        const float* __restrict__ sb, float* __restrict__ S) {
    int bn = blockIdx.x;
    int b = bn / NNODE, n = bn % NNODE;
    int tid = threadIdx.x;                // 0..511
    int s = tid >> 8;
    int c = (tid >> 4) & 15;
    int t = tid & 15;
    float xin = inp[(((size_t)b * 16 + t) * NNODE + n) * 2 + s];
    S[(size_t)bn * 512 + tid] = xin * sw[s * 16 + c] + sb[s * 16 + c];
}

// ---------------- dilated gated conv ----------------
__global__ void k_gated(const float* __restrict__ S, float* __restrict__ G,
                        const float* __restrict__ fw, const float* __restrict__ fb,
                        const float* __restrict__ gw, const float* __restrict__ gb,
                        int d, int Tin, int Ti) {
    int bn = blockIdx.x;
    int nthr = 32 * Ti;
    __shared__ float sx[512];
    __shared__ float sfw[1024], sgw[1024], sfb[32], sgb[32];
    int tid = threadIdx.x;
    int rowlen = 32 * Tin;
    for (int i = tid; i < rowlen; i += nthr) sx[i] = S[(size_t)bn * rowlen + i];
    for (int i = tid; i < 1024; i += nthr) { sfw[i] = fw[i]; sgw[i] = gw[i]; }
    for (int i = tid; i < 32; i += nthr)   { sfb[i] = fb[i]; sgb[i] = gb[i]; }
    __syncthreads();
    int s = tid / (16 * Ti);
    int r = tid % (16 * Ti);
    int o = r / Ti, t = r % Ti;
    float f = sfb[s * 16 + o], g = sgb[s * 16 + o];
    int base = s * 16 * Tin + t;
#pragma unroll
    for (int c = 0; c < 16; c++) {
        float xa = sx[base + c * Tin];
        float xb2 = sx[base + c * Tin + d];
        int wi = ((s * 16 + o) * 16 + c) * 2;
        f += sfw[wi] * xa + sfw[wi + 1] * xb2;
        g += sgw[wi] * xa + sgw[wi + 1] * xb2;
    }
    G[(size_t)bn * nthr + tid] = tanhf(f) * (1.f / (1.f + expf(-g)));
}

// ---------------- skip projection (stream 0 of G) ----------------
__global__ void k_skip(const float* __restrict__ G, const float* __restrict__ sw,
                       const float* __restrict__ sb, float* __restrict__ SK,
                       int Ti, int off) {
    int bn = blockIdx.x;
    int tid = threadIdx.x;
    __shared__ float sg[256];
    __shared__ float w_[136];
    int rl = 16 * Ti;
    for (int i = tid; i < rl; i += blockDim.x) sg[i] = G[(size_t)bn * (32 * Ti) + i];
    if (tid < 128) w_[tid] = sw[tid];
    if (tid < 8)   w_[128 + tid] = sb[tid];
    __syncthreads();
    int nout = 8 * Ti;
    for (int idx = tid; idx < nout; idx += blockDim.x) {
        int c = idx / Ti, t = idx % Ti;
        float acc = w_[128 + c];
#pragma unroll
        for (int k = 0; k < 16; k++) acc += w_[c * 16 + k] * sg[k * Ti + t];
        SK[(size_t)bn * 304 + off + idx] = acc;
    }
}

// ---------------- batched graph GEMM: Y[b] = A[b] @ X[b] ----------------
// A: [b][NNODE][NNODE] row-major.  X row v: X[b*NNODE*xstride + v*xstride + xoff + col]
__global__ void k_gemm(const float* __restrict__ Ab, const float* __restrict__ Xb,
                       float* __restrict__ Yb, int L,
                       int xstride, int xoff, int ystride, int yoff) {
    int b = blockIdx.z;
    const float* A = Ab + (size_t)b * NNODE * NNODE;
    const float* X = Xb + (size_t)b * NNODE * xstride;
    float* Y = Yb + (size_t)b * NNODE * ystride;
    int row0 = blockIdx.y * 64, col0 = blockIdx.x * 64;
    __shared__ float As[16][65];
    __shared__ float Xs[16][64];
    int tid = threadIdx.x;
    int tx = tid & 15, ty = tid >> 4;
    float acc[4][4] = {{0.f}};
    for (int k0 = 0; k0 < NNODE; k0 += 16) {
#pragma unroll
        for (int i = 0; i < 4; i++) {
            int idx = tid + i * 256;
            int m = idx >> 4, kk = idx & 15;
            int gr = row0 + m, gk = k0 + kk;
            As[kk][m] = (gr < NNODE && gk < NNODE) ? A[(size_t)gr * NNODE + gk] : 0.f;
        }
#pragma unroll
        for (int i = 0; i < 4; i++) {
            int idx = tid + i * 256;
            int kk = idx >> 6, j = idx & 63;
            int gk = k0 + kk, gc = col0 + j;
            Xs[kk][j] = (gk < NNODE && gc < L) ? X[(size_t)gk * xstride + xoff + gc] : 0.f;
        }
        __syncthreads();
#pragma unroll
        for (int kk = 0; kk < 16; kk++) {
            float ra[4], rx[4];
#pragma unroll
            for (int i = 0; i < 4; i++) ra[i] = As[kk][ty * 4 + i];
#pragma unroll
            for (int j = 0; j < 4; j++) rx[j] = Xs[kk][tx * 4 + j];
#pragma unroll
            for (int i = 0; i < 4; i++)
#pragma unroll
                for (int j = 0; j < 4; j++) acc[i][j] += ra[i] * rx[j];
        }
        __syncthreads();
    }
#pragma unroll
    for (int i = 0; i < 4; i++) {
        int gr = row0 + ty * 4 + i;
        if (gr >= NNODE) continue;
#pragma unroll
        for (int j = 0; j < 4; j++) {
            int gc = col0 + tx * 4 + j;
            if (gc < L) Y[(size_t)gr * ystride + yoff + gc] = acc[i][j];
        }
    }
}

// ---------------- gconv pointwise: g = W*[G, Y1, Y2] + b ----------------
__global__ void k_g01(const float* __restrict__ G, const float* __restrict__ Y1,
                      const float* __restrict__ Y2, const float* __restrict__ gw,
                      const float* __restrict__ gb, float* __restrict__ G01, int Ti) {
    int bn = blockIdx.x;
    int nthr = 32 * Ti;
    __shared__ float sg[512], sy1[512], sy2[512], sw_[1536], sb_[32];
    size_t base = (size_t)bn * nthr;
    int tid = threadIdx.x;
    sg[tid] = G[base + tid]; sy1[tid] = Y1[base + tid]; sy2[tid] = Y2[base + tid];
    for (int i = tid; i < 1536; i += nthr) sw_[i] = gw[i];
    if (tid < 32) sb_[tid] = gb[tid];
    __syncthreads();
    int s = tid / (16 * Ti);
    int r = tid % (16 * Ti);
    int o = r / Ti, t = r % Ti;
    float acc = sb_[s * 16 + o];
    const float* w = sw_ + (s * 16 + o) * 48;
    int cb = s * 16 * Ti + t;
#pragma unroll
    for (int c = 0; c < 16; c++)
        acc += w[c] * sg[cb + c * Ti] + w[16 + c] * sy1[cb + c * Ti] + w[32 + c] * sy2[cb + c * Ti];
    G01[base + tid] = acc;
}

// ---------------- residual/state update ----------------
__global__ void k_update(const float* __restrict__ Sin, const float* __restrict__ G01,
                         const float* __restrict__ Z1, const float* __restrict__ Z2,
                         const float* __restrict__ gaw, const float* __restrict__ gab,
                         float* __restrict__ Sout, int d, int Tin, int Ti) {
    int bn = blockIdx.x;
    int tid = threadIdx.x;
    int nthr = 32 * Ti;
    int rl = 16 * Ti;
    __shared__ float sg1[256], sz1[256], sz2[256], sw_[768], sb_[16];
    size_t gbase = (size_t)bn * nthr;
    for (int i = tid; i < rl; i += nthr) {
        sg1[i] = G01[gbase + rl + i];
        sz1[i] = Z1[(size_t)bn * rl + i];
        sz2[i] = Z2[(size_t)bn * rl + i];
    }
    for (int i = tid; i < 768; i += nthr) sw_[i] = gaw[i];
    if (tid < 16) sb_[tid] = gab[tid];
    __syncthreads();
    int s = tid / rl;
    int r = tid % rl;
    int c = r / Ti, t = r % Ti;
    float out;
    if (s == 0) {
        float xap = sb_[c];
        const float* w = sw_ + c * 48;
#pragma unroll
        for (int k = 0; k < 16; k++)
            xap += w[k] * sg1[k * Ti + t] + w[16 + k] * sz1[k * Ti + t] + w[32 + k] * sz2[k * Ti + t];
        float g0 = G01[gbase + c * Ti + t];
        float r0 = Sin[(size_t)bn * (32 * Tin) + c * Tin + (t + d)];
        out = (2.f * g0 + xap + r0) * BN_SCALE;
    } else {
        float r1 = Sin[(size_t)bn * (32 * Tin) + (16 + c) * Tin + (t + d)];
        out = r1 * BN_SCALE;
    }
    Sout[gbase + tid] = out;
}

// ---------------- end convs: out = W2 @ relu(W1 @ relu(skip) + b1) + b2 ----------------
__global__ void k_end(const float* __restrict__ SK, const float* __restrict__ e1w,
                      const float* __restrict__ e1b, const float* __restrict__ e2w,
                      const float* __restrict__ e2b, float* __restrict__ out) {
    int warp = threadIdx.x >> 5, lane = threadIdx.x & 31;
    int bn = blockIdx.x * 4 + warp;
    if (bn >= BB * NNODE) return;
    int b = bn / NNODE, n = bn % NNODE;
    const float* sk = SK + (size_t)bn * 304;
    float acc[16];
#pragma unroll
    for (int o = 0; o < 16; o++) acc[o] = 0.f;
    for (int k = lane; k < 304; k += 32) {
        float v = fmaxf(sk[k], 0.f);
#pragma unroll
        for (int o = 0; o < 16; o++) acc[o] += e1w[o * 304 + k] * v;
    }
#pragma unroll
    for (int o = 0; o < 16; o++) {
#pragma unroll
        for (int off = 16; off > 0; off >>= 1)
            acc[o] += __shfl_xor_sync(0xffffffff, acc[o], off);
    }
    if (lane == 0) {
        float e1[16];
#pragma unroll
        for (int o = 0; o < 16; o++) e1[o] = fmaxf(acc[o] + e1b[o], 0.f);
#pragma unroll
        for (int o2 = 0; o2 < 3; o2++) {
            float s = e2b[o2];
#pragma unroll
            for (int o = 0; o < 16; o++) s += e2w[o2 * 16 + o] * e1[o];
            out[((size_t)b * 3 + o2) * NNODE + n] = s;
        }
    }
}

// ---------------- host orchestration ----------------
extern "C" void kernel_launch(void* const* d_in, const int* in_sizes, int n_in,
                              void* d_out, int out_size) {
    const float* inputs  = (const float*)d_in[0];
    const int*   ind     = (const int*)  d_in[1];
    const float* start_w = (const float*)d_in[2];
    const float* start_b = (const float*)d_in[3];
    const float* p1      = (const float*)d_in[4];
    const float* p2      = (const float*)d_in[5];
    const float* p3      = (const float*)d_in[6];
    const float* pk      = (const float*)d_in[7];
    const float* a2p1    = (const float*)d_in[8];
    const float* a2p2    = (const float*)d_in[9];
    const float* a2p3    = (const float*)d_in[10];
    const float* a2pk    = (const float*)d_in[11];
    const float* filt_w  = (const float*)d_in[12];
    const float* filt_b  = (const float*)d_in[13];
    const float* gate_w  = (const float*)d_in[14];
    const float* gate_b  = (const float*)d_in[15];
    const float* gconv_w = (const float*)d_in[16];
    const float* gconv_b = (const float*)d_in[17];
    const float* ga_w    = (const float*)d_in[18];
    const float* ga_b    = (const float*)d_in[19];
    const float* skip_w  = (const float*)d_in[20];
    const float* skip_b  = (const float*)d_in[21];
    const float* end1_w  = (const float*)d_in[22];
    const float* end1_b  = (const float*)d_in[23];
    const float* end2_w  = (const float*)d_in[24];
    const float* end2_b  = (const float*)d_in[25];
    float* out = (float*)d_out;

    float *adp, *adp2, *T1, *T2, *M1, *M2, *S0, *S1, *G, *Y1, *Y2, *G01, *Z1, *Z2, *SK;
    cudaGetSymbolAddress((void**)&adp,  g_adp);
    cudaGetSymbolAddress((void**)&adp2, g_adp2);
    cudaGetSymbolAddress((void**)&T1,   g_T1);
    cudaGetSymbolAddress((void**)&T2,   g_T2);
    cudaGetSymbolAddress((void**)&M1,   g_M1);
    cudaGetSymbolAddress((void**)&M2,   g_M2);
    cudaGetSymbolAddress((void**)&S0,   g_S0);
    cudaGetSymbolAddress((void**)&S1,   g_S1);
    cudaGetSymbolAddress((void**)&G,    g_G);
    cudaGetSymbolAddress((void**)&Y1,   g_Y1);
    cudaGetSymbolAddress((void**)&Y2,   g_Y2);
    cudaGetSymbolAddress((void**)&G01,  g_G01);
    cudaGetSymbolAddress((void**)&Z1,   g_Z1);
    cudaGetSymbolAddress((void**)&Z2,   g_Z2);
    cudaGetSymbolAddress((void**)&SK,   g_SK);

    // graph construction
    k_T<<<BB, 256>>>(p1, pk, ind, T1);
    k_T<<<BB, 256>>>(a2p1, a2pk, ind, T2);
    int nM = BB * NNODE * DIMS;
    k_M<<<(nM + 255) / 256, 256>>>(p2, T1, M1);
    k_M<<<(nM + 255) / 256, 256>>>(a2p2, T2, M2);
    k_adp<<<BB * NNODE, 256>>>(M1, p3, adp);
    k_adp<<<BB * NNODE, 256>>>(M2, a2p3, adp2);

    // start embedding
    k_start<<<BB * NNODE, 512>>>(inputs, start_w, start_b, S0);

    const int dil[4]     = {1, 2, 4, 8};
    const int skipoff[4] = {184, 80, 8, 0};
    float* Sin = S0;
    float* Sout = S1;
    int Tin = 16;
    for (int i = 0; i < 4; i++) {
        int d = dil[i];
        int Ti = Tin - d;
        k_gated<<<BB * NNODE, 32 * Ti>>>(Sin, G,
            filt_w + i * 1024, filt_b + i * 32,
            gate_w + i * 1024, gate_b + i * 32, d, Tin, Ti);
        k_skip<<<BB * NNODE, 128>>>(G, skip_w + i * 128, skip_b + i * 8, SK, Ti, skipoff[i]);
        if (i < 3) {
            int L = 32 * Ti;
            dim3 grid((L + 63) / 64, 8, BB);
            k_gemm<<<grid, 256>>>(adp, G,  Y1, L, L, 0, L, 0);
            k_gemm<<<grid, 256>>>(adp, Y1, Y2, L, L, 0, L, 0);
            k_g01<<<BB * NNODE, 32 * Ti>>>(G, Y1, Y2,
                gconv_w + i * 1536, gconv_b + i * 32, G01, Ti);
            int L2 = 16 * Ti;
            dim3 grid2((L2 + 63) / 64, 8, BB);
            k_gemm<<<grid2, 256>>>(adp2, G01, Z1, L2, 32 * Ti, 16 * Ti, L2, 0);
            k_gemm<<<grid2, 256>>>(adp2, Z1,  Z2, L2, L2, 0, L2, 0);
            k_update<<<BB * NNODE, 32 * Ti>>>(Sin, G01, Z1, Z2,
                ga_w + i * 768, ga_b + i * 16, Sout, d, Tin, Ti);
            float* tmp = Sin; Sin = Sout; Sout = tmp;
        }
        Tin = Ti;
    }

    k_end<<<(BB * NNODE + 3) / 4, 128>>>(SK, end1_w, end1_b, end2_w, end2_b, out);
}

// round 2
// speedup vs baseline: 1.5171x; 1.5171x over previous
#include <cuda_runtime.h>
#include <math.h>
#include <stdint.h>

#define BB 64
#define NNODE 500
#define DIMS 40
#define BN_SCALE 0.99999500003749968750f  // 1/sqrt(1+1e-5)

// ---------------- scratch (device globals; no allocation allowed) ----------------
__device__ float g_adp [BB * NNODE * NNODE];   // 64 MB
__device__ float g_adp2[BB * NNODE * NNODE];   // 64 MB
__device__ float g_T1[BB * DIMS * DIMS];
__device__ float g_T2[BB * DIMS * DIMS];
__device__ float g_M1[BB * NNODE * DIMS];
__device__ float g_M2[BB * NNODE * DIMS];
__device__ float g_S0 [BB * NNODE * 512];
__device__ float g_S1 [BB * NNODE * 512];
__device__ float g_G  [BB * NNODE * 512];
__device__ float g_Y1 [BB * NNODE * 512];
__device__ float g_Y2 [BB * NNODE * 512];
__device__ float g_G01[BB * NNODE * 512];
__device__ float g_Z1 [BB * NNODE * 256];
__device__ float g_Z2 [BB * NNODE * 256];
__device__ float g_SK [BB * NNODE * 304];

// ---------------- graph construction ----------------
__global__ void k_T(const float* __restrict__ p1, const float* __restrict__ pk,
                    const int* __restrict__ ind, float* __restrict__ Tout) {
    int b = blockIdx.x;
    __shared__ float te[DIMS];
    int day = ind[b];
    if (threadIdx.x < DIMS) te[threadIdx.x] = p1[day * DIMS + threadIdx.x];
    __syncthreads();
    for (int jk = threadIdx.x; jk < DIMS * DIMS; jk += blockDim.x) {
        float s = 0.f;
#pragma unroll
        for (int i = 0; i < DIMS; i++) s += te[i] * pk[i * DIMS * DIMS + jk];
        Tout[b * DIMS * DIMS + jk] = s;
    }
}

__global__ void k_M(const float* __restrict__ p2, const float* __restrict__ T,
                    float* __restrict__ M) {
    int idx = blockIdx.x * blockDim.x + threadIdx.x;
    if (idx >= BB * NNODE * DIMS) return;
    int k = idx % DIMS;
    int w = (idx / DIMS) % NNODE;
    int b = idx / (DIMS * NNODE);
    float s = 0.f;
    const float* Tb = T + b * DIMS * DIMS;
#pragma unroll
    for (int j = 0; j < DIMS; j++) s += p2[w * DIMS + j] * Tb[j * DIMS + k];
    M[idx] = s;
}

__global__ void k_adp(const float* __restrict__ M, const float* __restrict__ p3,
                      float* __restrict__ A) {
    int bw = blockIdx.x;                  // b*NNODE + w
    __shared__ float mrow[DIMS];
    __shared__ float vals[NNODE];
    __shared__ float red[256];
    int tid = threadIdx.x;
    if (tid < DIMS) mrow[tid] = M[(size_t)bw * DIMS + tid];
    __syncthreads();
    for (int v = tid; v < NNODE; v += 256) {
        float s = 0.f;
#pragma unroll
        for (int k = 0; k < DIMS; k++) s += p3[v * DIMS + k] * mrow[k];
        vals[v] = fmaxf(s, 0.f);
    }
    __syncthreads();
    float m = 0.f;
    for (int v = tid; v < NNODE; v += 256) m = fmaxf(m, vals[v]);
    red[tid] = m; __syncthreads();
    for (int s2 = 128; s2 > 0; s2 >>= 1) {
        if (tid < s2) red[tid] = fmaxf(red[tid], red[tid + s2]);
        __syncthreads();
    }
    m = red[0];
    __syncthreads();
    float sum = 0.f;
    for (int v = tid; v < NNODE; v += 256) {
        float e = expf(vals[v] - m);
        vals[v] = e; sum += e;
    }
    red[tid] = sum; __syncthreads();
    for (int s2 = 128; s2 > 0; s2 >>= 1) {
        if (tid < s2) red[tid] += red[tid + s2];
        __syncthreads();
    }
    float inv = 1.f / red[0];
    float* Ar = A + (size_t)bw * NNODE;
    for (int v = tid; v < NNODE; v += 256) Ar[v] = vals[v] * inv;
}

// ---------------- start embedding ----------------
__global__ void k_start(const float* __restrict__ inp, const float* __restrict__ sw,
                        const float* __restrict__ sb, float* __restrict__ S) {
    int bn = blockIdx.x;
    int b = bn / NNODE, n = bn % NNODE;
    int tid = threadIdx.x;                // 0..511
    int s = tid >> 8;
    int c = (tid >> 4) & 15;
    int t = tid & 15;
    float xin = inp[(((size_t)b * 16 + t) * NNODE + n) * 2 + s];
    S[(size_t)bn * 512 + tid] = xin * sw[s * 16 + c] + sb[s * 16 + c];
}

// ---------------- dilated gated conv ----------------
__global__ void k_gated(const float* __restrict__ S, float* __restrict__ G,
                        const float* __restrict__ fw, const float* __restrict__ fb,
                        const float* __restrict__ gw, const float* __restrict__ gb,
                        int d, int Tin, int Ti) {
    int bn = blockIdx.x;
    int nthr = 32 * Ti;
    __shared__ float sx[512];
    __shared__ float sfw[1024], sgw[1024], sfb[32], sgb[32];
    int tid = threadIdx.x;
    int rowlen = 32 * Tin;
    for (int i = tid; i < rowlen; i += nthr) sx[i] = S[(size_t)bn * rowlen + i];
    for (int i = tid; i < 1024; i += nthr) { sfw[i] = fw[i]; sgw[i] = gw[i]; }
    for (int i = tid; i < 32; i += nthr)   { sfb[i] = fb[i]; sgb[i] = gb[i]; }
    __syncthreads();
    int s = tid / (16 * Ti);
    int r = tid % (16 * Ti);
    int o = r / Ti, t = r % Ti;
    float f = sfb[s * 16 + o], g = sgb[s * 16 + o];
    int base = s * 16 * Tin + t;
#pragma unroll
    for (int c = 0; c < 16; c++) {
        float xa = sx[base + c * Tin];
        float xb2 = sx[base + c * Tin + d];
        int wi = ((s * 16 + o) * 16 + c) * 2;
        f += sfw[wi] * xa + sfw[wi + 1] * xb2;
        g += sgw[wi] * xa + sgw[wi + 1] * xb2;
    }
    G[(size_t)bn * nthr + tid] = tanhf(f) * (1.f / (1.f + expf(-g)));
}

// ---------------- skip projection (stream 0 of G) ----------------
__global__ void k_skip(const float* __restrict__ G, const float* __restrict__ sw,
                       const float* __restrict__ sb, float* __restrict__ SK,
                       int Ti, int off) {
    int bn = blockIdx.x;
    int tid = threadIdx.x;
    __shared__ float sg[256];
    __shared__ float w_[136];
    int rl = 16 * Ti;
    for (int i = tid; i < rl; i += blockDim.x) sg[i] = G[(size_t)bn * (32 * Ti) + i];
    if (tid < 128) w_[tid] = sw[tid];
    if (tid < 8)   w_[128 + tid] = sb[tid];
    __syncthreads();
    int nout = 8 * Ti;
    for (int idx = tid; idx < nout; idx += blockDim.x) {
        int c = idx / Ti, t = idx % Ti;
        float acc = w_[128 + c];
#pragma unroll
        for (int k = 0; k < 16; k++) acc += w_[c * 16 + k] * sg[k * Ti + t];
        SK[(size_t)bn * 304 + off + idx] = acc;
    }
}

// ---------------- tensor-core batched graph GEMM (tf32) ----------------
// Y[b] = A[b] @ X[b].  A: [b][500][500] row-major.
// X row v at Xb + b*500*xstride + v*xstride + xoff; Y likewise.
__device__ __forceinline__ uint32_t f2tf(float x) {
    uint32_t u;
    asm("cvt.rna.tf32.f32 %0, %1;" : "=r"(u) : "f"(x));
    return u;
}

__device__ __forceinline__ void mma_tf32(float* c, const uint32_t* a, const uint32_t* b) {
    asm volatile(
        "mma.sync.aligned.m16n8k8.row.col.f32.tf32.tf32.f32 "
        "{%0,%1,%2,%3}, {%4,%5,%6,%7}, {%8,%9}, {%0,%1,%2,%3};"
        : "+f"(c[0]), "+f"(c[1]), "+f"(c[2]), "+f"(c[3])
        : "r"(a[0]), "r"(a[1]), "r"(a[2]), "r"(a[3]), "r"(b[0]), "r"(b[1]));
}

#define GP 136   // smem row pad: stride%32==8 -> conflict-free fragment loads

__global__ __launch_bounds__(256) void k_gemm_tc(
        const float* __restrict__ Ab, const float* __restrict__ Xb,
        float* __restrict__ Yb, int L,
        int xstride, int xoff, int ystride, int yoff) {
    int b = blockIdx.z;
    const float* A = Ab + (size_t)b * NNODE * NNODE;
    const float* X = Xb + (size_t)b * NNODE * xstride + xoff;
    float* Y = Yb + (size_t)b * NNODE * ystride + yoff;
    int row0 = blockIdx.y * 128, col0 = blockIdx.x * 128;

    __shared__ uint32_t As[16][GP];
    __shared__ uint32_t Bs[16][GP];

    int tid = threadIdx.x;
    int lane = tid & 31, wid = tid >> 5;
    int warpM = wid >> 1, warpN = wid & 1;   // 4 x 2 warps -> 32 x 64 warp tile
    int g = lane >> 2, r = lane & 3;

    // A load pattern: kk fixed per thread, m = aM + i*16
    int aKK = tid & 15, aM = tid >> 4;
    // B load pattern: n fixed per thread, kk = bK + i*2
    int bN = tid & 127, bK = tid >> 7;

    float ra[8], rb[8];
    float acc[2][8][4];
#pragma unroll
    for (int mi = 0; mi < 2; mi++)
#pragma unroll
        for (int ni = 0; ni < 8; ni++)
#pragma unroll
            for (int q = 0; q < 4; q++) acc[mi][ni][q] = 0.f;

    // ---- initial tile (k0 = 0) ----
#pragma unroll
    for (int i = 0; i < 8; i++) {
        int m = aM + i * 16;
        ra[i] = (row0 + m < NNODE && aKK < NNODE) ? A[(size_t)(row0 + m) * NNODE + aKK] : 0.f;
    }
#pragma unroll
    for (int i = 0; i < 8; i++) {
        int kk = bK + i * 2;
        rb[i] = (kk < NNODE && col0 + bN < L) ? X[(size_t)kk * xstride + col0 + bN] : 0.f;
    }
#pragma unroll
    for (int i = 0; i < 8; i++) As[aKK][aM + i * 16] = f2tf(ra[i]);
#pragma unroll
    for (int i = 0; i < 8; i++) Bs[bK + i * 2][bN] = f2tf(rb[i]);
    __syncthreads();

    for (int k0 = 0; k0 < NNODE; k0 += 16) {
        bool nxt = (k0 + 16) < NNODE;
        if (nxt) {
            int k1 = k0 + 16;
#pragma unroll
            for (int i = 0; i < 8; i++) {
                int m = aM + i * 16;
                ra[i] = (row0 + m < NNODE && k1 + aKK < NNODE)
                        ? A[(size_t)(row0 + m) * NNODE + k1 + aKK] : 0.f;
            }
#pragma unroll
            for (int i = 0; i < 8; i++) {
                int kk = k1 + bK + i * 2;
                rb[i] = (kk < NNODE && col0 + bN < L) ? X[(size_t)kk * xstride + col0 + bN] : 0.f;
            }
        }
        // compute from smem
#pragma unroll
        for (int kc = 0; kc < 16; kc += 8) {
            uint32_t af[2][4], bf[8][2];
#pragma unroll
            for (int mi = 0; mi < 2; mi++) {
                int mb = warpM * 32 + mi * 16;
                af[mi][0] = As[kc + r][mb + g];
                af[mi][1] = As[kc + r][mb + g + 8];
                af[mi][2] = As[kc + r + 4][mb + g];
                af[mi][3] = As[kc + r + 4][mb + g + 8];
            }
#pragma unroll
            for (int ni = 0; ni < 8; ni++) {
                int nb = warpN * 64 + ni * 8;
                bf[ni][0] = Bs[kc + r][nb + g];
                bf[ni][1] = Bs[kc + r + 4][nb + g];
            }
#pragma unroll
            for (int mi = 0; mi < 2; mi++)
#pragma unroll
                for (int ni = 0; ni < 8; ni++)
                    mma_tf32(acc[mi][ni], af[mi], bf[ni]);
        }
        __syncthreads();
        if (nxt) {
#pragma unroll
            for (int i = 0; i < 8; i++) As[aKK][aM + i * 16] = f2tf(ra[i]);
#pragma unroll
            for (int i = 0; i < 8; i++) Bs[bK + i * 2][bN] = f2tf(rb[i]);
            __syncthreads();
        }
    }

    // epilogue
#pragma unroll
    for (int mi = 0; mi < 2; mi++) {
#pragma unroll
        for (int ni = 0; ni < 8; ni++) {
            int row = row0 + warpM * 32 + mi * 16 + g;
            int col = col0 + warpN * 64 + ni * 8 + 2 * r;
            if (row < NNODE) {
                if (col < L)     Y[(size_t)row * ystride + col]     = acc[mi][ni][0];
                if (col + 1 < L) Y[(size_t)row * ystride + col + 1] = acc[mi][ni][1];
            }
            if (row + 8 < NNODE) {
                if (col < L)     Y[(size_t)(row + 8) * ystride + col]     = acc[mi][ni][2];
                if (col + 1 < L) Y[(size_t)(row + 8) * ystride + col + 1] = acc[mi][ni][3];
            }
        }
    }
}

// ---------------- gconv pointwise: g = W*[G, Y1, Y2] + b ----------------
__global__ void k_g01(const float* __restrict__ G, const float* __restrict__ Y1,
                      const float* __restrict__ Y2, const float* __restrict__ gw,
                      const float* __restrict__ gb, float* __restrict__ G01, int Ti) {
    int bn = blockIdx.x;
    int nthr = 32 * Ti;
    __shared__ float sg[512], sy1[512], sy2[512], sw_[1536], sb_[32];
    size_t base = (size_t)bn * nthr;
    int tid = threadIdx.x;
    sg[tid] = G[base + tid]; sy1[tid] = Y1[base + tid]; sy2[tid] = Y2[base + tid];
    for (int i = tid; i < 1536; i += nthr) sw_[i] = gw[i];
    if (tid < 32) sb_[tid] = gb[tid];
    __syncthreads();
    int s = tid / (16 * Ti);
    int r = tid % (16 * Ti);
    int o = r / Ti, t = r % Ti;
    float acc = sb_[s * 16 + o];
    const float* w = sw_ + (s * 16 + o) * 48;
    int cb = s * 16 * Ti + t;
#pragma unroll
    for (int c = 0; c < 16; c++)
        acc += w[c] * sg[cb + c * Ti] + w[16 + c] * sy1[cb + c * Ti] + w[32 + c] * sy2[cb + c * Ti];
    G01[base + tid] = acc;
}

// ---------------- residual/state update ----------------
__global__ void k_update(const float* __restrict__ Sin, const float* __restrict__ G01,
                         const float* __restrict__ Z1, const float* __restrict__ Z2,
                         const float* __restrict__ gaw, const float* __restrict__ gab,
                         float* __restrict__ Sout, int d, int Tin, int Ti) {
    int bn = blockIdx.x;
    int tid = threadIdx.x;
    int nthr = 32 * Ti;
    int rl = 16 * Ti;
    __shared__ float sg1[256], sz1[256], sz2[256], sw_[768], sb_[16];
    size_t gbase = (size_t)bn * nthr;
    for (int i = tid; i < rl; i += nthr) {
        sg1[i] = G01[gbase + rl + i];
        sz1[i] = Z1[(size_t)bn * rl + i];
        sz2[i] = Z2[(size_t)bn * rl + i];
    }
    for (int i = tid; i < 768; i += nthr) sw_[i] = gaw[i];
    if (tid < 16) sb_[tid] = gab[tid];
    __syncthreads();
    int s = tid / rl;
    int r = tid % rl;
    int c = r / Ti, t = r % Ti;
    float out;
    if (s == 0) {
        float xap = sb_[c];
        const float* w = sw_ + c * 48;
#pragma unroll
        for (int k = 0; k < 16; k++)
            xap += w[k] * sg1[k * Ti + t] + w[16 + k] * sz1[k * Ti + t] + w[32 + k] * sz2[k * Ti + t];
        float g0 = G01[gbase + c * Ti + t];
        float r0 = Sin[(size_t)bn * (32 * Tin) + c * Tin + (t + d)];
        out = (2.f * g0 + xap + r0) * BN_SCALE;
    } else {
        float r1 = Sin[(size_t)bn * (32 * Tin) + (16 + c) * Tin + (t + d)];
        out = r1 * BN_SCALE;
    }
    Sout[gbase + tid] = out;
}

// ---------------- end convs ----------------
__global__ void k_end(const float* __restrict__ SK, const float* __restrict__ e1w,
                      const float* __restrict__ e1b, const float* __restrict__ e2w,
                      const float* __restrict__ e2b, float* __restrict__ out) {
    int warp = threadIdx.x >> 5, lane = threadIdx.x & 31;
    int bn = blockIdx.x * 4 + warp;
    if (bn >= BB * NNODE) return;
    int b = bn / NNODE, n = bn % NNODE;
    const float* sk = SK + (size_t)bn * 304;
    float acc[16];
#pragma unroll
    for (int o = 0; o < 16; o++) acc[o] = 0.f;
    for (int k = lane; k < 304; k += 32) {
        float v = fmaxf(sk[k], 0.f);
#pragma unroll
        for (int o = 0; o < 16; o++) acc[o] += e1w[o * 304 + k] * v;
    }
#pragma unroll
    for (int o = 0; o < 16; o++) {
#pragma unroll
        for (int off = 16; off > 0; off >>= 1)
            acc[o] += __shfl_xor_sync(0xffffffff, acc[o], off);
    }
    if (lane == 0) {
        float e1[16];
#pragma unroll
        for (int o = 0; o < 16; o++) e1[o] = fmaxf(acc[o] + e1b[o], 0.f);
#pragma unroll
        for (int o2 = 0; o2 < 3; o2++) {
            float s = e2b[o2];
#pragma unroll
            for (int o = 0; o < 16; o++) s += e2w[o2 * 16 + o] * e1[o];
            out[((size_t)b * 3 + o2) * NNODE + n] = s;
        }
    }
}

// ---------------- host orchestration ----------------
extern "C" void kernel_launch(void* const* d_in, const int* in_sizes, int n_in,
                              void* d_out, int out_size) {
    const float* inputs  = (const float*)d_in[0];
    const int*   ind     = (const int*)  d_in[1];
    const float* start_w = (const float*)d_in[2];
    const float* start_b = (const float*)d_in[3];
    const float* p1      = (const float*)d_in[4];
    const float* p2      = (const float*)d_in[5];
    const float* p3      = (const float*)d_in[6];
    const float* pk      = (const float*)d_in[7];
    const float* a2p1    = (const float*)d_in[8];
    const float* a2p2    = (const float*)d_in[9];
    const float* a2p3    = (const float*)d_in[10];
    const float* a2pk    = (const float*)d_in[11];
    const float* filt_w  = (const float*)d_in[12];
    const float* filt_b  = (const float*)d_in[13];
    const float* gate_w  = (const float*)d_in[14];
    const float* gate_b  = (const float*)d_in[15];
    const float* gconv_w = (const float*)d_in[16];
    const float* gconv_b = (const float*)d_in[17];
    const float* ga_w    = (const float*)d_in[18];
    const float* ga_b    = (const float*)d_in[19];
    const float* skip_w  = (const float*)d_in[20];
    const float* skip_b  = (const float*)d_in[21];
    const float* end1_w  = (const float*)d_in[22];
    const float* end1_b  = (const float*)d_in[23];
    const float* end2_w  = (const float*)d_in[24];
    const float* end2_b  = (const float*)d_in[25];
    float* out = (float*)d_out;

    float *adp, *adp2, *T1, *T2, *M1, *M2, *S0, *S1, *G, *Y1, *Y2, *G01, *Z1, *Z2, *SK;
    cudaGetSymbolAddress((void**)&adp,  g_adp);
    cudaGetSymbolAddress((void**)&adp2, g_adp2);
    cudaGetSymbolAddress((void**)&T1,   g_T1);
    cudaGetSymbolAddress((void**)&T2,   g_T2);
    cudaGetSymbolAddress((void**)&M1,   g_M1);
    cudaGetSymbolAddress((void**)&M2,   g_M2);
    cudaGetSymbolAddress((void**)&S0,   g_S0);
    cudaGetSymbolAddress((void**)&S1,   g_S1);
    cudaGetSymbolAddress((void**)&G,    g_G);
    cudaGetSymbolAddress((void**)&Y1,   g_Y1);
    cudaGetSymbolAddress((void**)&Y2,   g_Y2);
    cudaGetSymbolAddress((void**)&G01,  g_G01);
    cudaGetSymbolAddress((void**)&Z1,   g_Z1);
    cudaGetSymbolAddress((void**)&Z2,   g_Z2);
    cudaGetSymbolAddress((void**)&SK,   g_SK);

    // graph construction
    k_T<<<BB, 256>>>(p1, pk, ind, T1);
    k_T<<<BB, 256>>>(a2p1, a2pk, ind, T2);
    int nM = BB * NNODE * DIMS;
    k_M<<<(nM + 255) / 256, 256>>>(p2, T1, M1);
    k_M<<<(nM + 255) / 256, 256>>>(a2p2, T2, M2);
    k_adp<<<BB * NNODE, 256>>>(M1, p3, adp);
    k_adp<<<BB * NNODE, 256>>>(M2, a2p3, adp2);

    // start embedding
    k_start<<<BB * NNODE, 512>>>(inputs, start_w, start_b, S0);

    const int dil[4]     = {1, 2, 4, 8};
    const int skipoff[4] = {184, 80, 8, 0};
    float* Sin = S0;
    float* Sout = S1;
    int Tin = 16;
    for (int i = 0; i < 4; i++) {
        int d = dil[i];
        int Ti = Tin - d;
        k_gated<<<BB * NNODE, 32 * Ti>>>(Sin, G,
            filt_w + i * 1024, filt_b + i * 32,
            gate_w + i * 1024, gate_b + i * 32, d, Tin, Ti);
        k_skip<<<BB * NNODE, 128>>>(G, skip_w + i * 128, skip_b + i * 8, SK, Ti, skipoff[i]);
        if (i < 3) {
            int L = 32 * Ti;
            dim3 grid((L + 127) / 128, (NNODE + 127) / 128, BB);
            k_gemm_tc<<<grid, 256>>>(adp, G,  Y1, L, L, 0, L, 0);
            k_gemm_tc<<<grid, 256>>>(adp, Y1, Y2, L, L, 0, L, 0);
            k_g01<<<BB * NNODE, 32 * Ti>>>(G, Y1, Y2,
                gconv_w + i * 1536, gconv_b + i * 32, G01, Ti);
            int L2 = 16 * Ti;
            dim3 grid2((L2 + 127) / 128, (NNODE + 127) / 128, BB);
            k_gemm_tc<<<grid2, 256>>>(adp2, G01, Z1, L2, 32 * Ti, 16 * Ti, L2, 0);
            k_gemm_tc<<<grid2, 256>>>(adp2, Z1,  Z2, L2, L2, 0, L2, 0);
            k_update<<<BB * NNODE, 32 * Ti>>>(Sin, G01, Z1, Z2,
                ga_w + i * 768, ga_b + i * 16, Sout, d, Tin, Ti);
            float* tmp = Sin; Sin = Sout; Sout = tmp;
        }
        Tin = Ti;
    }

    k_end<<<(BB * NNODE + 3) / 4, 128>>>(SK, end1_w, end1_b, end2_w, end2_b, out);
}

// round 3
// speedup vs baseline: 1.6543x; 1.0905x over previous
#include <cuda_runtime.h>
#include <math.h>
#include <stdint.h>

#define BB 64
#define NNODE 500
#define DIMS 40
#define BN_SCALE 0.99999500003749968750f  // 1/sqrt(1+1e-5)

// ---------------- scratch (device globals; no allocation allowed) ----------------
__device__ float g_adp [BB * NNODE * NNODE];   // 64 MB
__device__ float g_adp2[BB * NNODE * NNODE];   // 64 MB
__device__ float g_T1[BB * DIMS * DIMS];
__device__ float g_T2[BB * DIMS * DIMS];
__device__ float g_M1[BB * NNODE * DIMS];
__device__ float g_M2[BB * NNODE * DIMS];
__device__ float g_S0 [BB * NNODE * 512];
__device__ float g_S1 [BB * NNODE * 512];
__device__ float g_G  [BB * NNODE * 512];
__device__ float g_Y1 [BB * NNODE * 512];
__device__ float g_Y2 [BB * NNODE * 512];
__device__ float g_G01[BB * NNODE * 512];
__device__ float g_Z1 [BB * NNODE * 256];
__device__ float g_Z2 [BB * NNODE * 256];
__device__ float g_SK [BB * NNODE * 304];

// ---------------- graph construction ----------------
__global__ void k_T(const float* __restrict__ p1, const float* __restrict__ pk,
                    const int* __restrict__ ind, float* __restrict__ Tout) {
    int b = blockIdx.x;
    __shared__ float te[DIMS];
    int day = ind[b];
    if (threadIdx.x < DIMS) te[threadIdx.x] = p1[day * DIMS + threadIdx.x];
    __syncthreads();
    for (int jk = threadIdx.x; jk < DIMS * DIMS; jk += blockDim.x) {
        float s = 0.f;
#pragma unroll
        for (int i = 0; i < DIMS; i++) s += te[i] * pk[i * DIMS * DIMS + jk];
        Tout[b * DIMS * DIMS + jk] = s;
    }
}

__global__ void k_M(const float* __restrict__ p2, const float* __restrict__ T,
                    float* __restrict__ M) {
    int idx = blockIdx.x * blockDim.x + threadIdx.x;
    if (idx >= BB * NNODE * DIMS) return;
    int k = idx % DIMS;
    int w = (idx / DIMS) % NNODE;
    int b = idx / (DIMS * NNODE);
    float s = 0.f;
    const float* Tb = T + b * DIMS * DIMS;
#pragma unroll
    for (int j = 0; j < DIMS; j++) s += p2[w * DIMS + j] * Tb[j * DIMS + k];
    M[idx] = s;
}

__global__ void k_adp(const float* __restrict__ M, const float* __restrict__ p3,
                      float* __restrict__ A) {
    int bw = blockIdx.x;                  // b*NNODE + w
    __shared__ float mrow[DIMS];
    __shared__ float vals[NNODE];
    __shared__ float red[256];
    int tid = threadIdx.x;
    if (tid < DIMS) mrow[tid] = M[(size_t)bw * DIMS + tid];
    __syncthreads();
    for (int v = tid; v < NNODE; v += 256) {
        float s = 0.f;
#pragma unroll
        for (int k = 0; k < DIMS; k++) s += p3[v * DIMS + k] * mrow[k];
        vals[v] = fmaxf(s, 0.f);
    }
    __syncthreads();
    float m = 0.f;
    for (int v = tid; v < NNODE; v += 256) m = fmaxf(m, vals[v]);
    red[tid] = m; __syncthreads();
    for (int s2 = 128; s2 > 0; s2 >>= 1) {
        if (tid < s2) red[tid] = fmaxf(red[tid], red[tid + s2]);
        __syncthreads();
    }
    m = red[0];
    __syncthreads();
    float sum = 0.f;
    for (int v = tid; v < NNODE; v += 256) {
        float e = expf(vals[v] - m);
        vals[v] = e; sum += e;
    }
    red[tid] = sum; __syncthreads();
    for (int s2 = 128; s2 > 0; s2 >>= 1) {
        if (tid < s2) red[tid] += red[tid + s2];
        __syncthreads();
    }
    float inv = 1.f / red[0];
    float* Ar = A + (size_t)bw * NNODE;
    for (int v = tid; v < NNODE; v += 256) Ar[v] = vals[v] * inv;
}

// ---------------- start embedding ----------------
__global__ void k_start(const float* __restrict__ inp, const float* __restrict__ sw,
                        const float* __restrict__ sb, float* __restrict__ S) {
    int bn = blockIdx.x;
    int b = bn / NNODE, n = bn % NNODE;
    int tid = threadIdx.x;                // 0..511
    int s = tid >> 8;
    int c = (tid >> 4) & 15;
    int t = tid & 15;
    float xin = inp[(((size_t)b * 16 + t) * NNODE + n) * 2 + s];
    S[(size_t)bn * 512 + tid] = xin * sw[s * 16 + c] + sb[s * 16 + c];
}

// ---------------- dilated gated conv + fused skip projection ----------------
__global__ void k_gated(const float* __restrict__ S, float* __restrict__ G,
                        const float* __restrict__ fw, const float* __restrict__ fb,
                        const float* __restrict__ gw, const float* __restrict__ gb,
                        const float* __restrict__ skw, const float* __restrict__ skb,
                        float* __restrict__ SK, int skoff,
                        int d, int Tin, int Ti) {
    int bn = blockIdx.x;
    int nthr = 32 * Ti;
    __shared__ float sx[512];
    __shared__ float sfw[1024], sgw[1024], sfb[32], sgb[32];
    __shared__ float sG0[256];          // stream-0 gated output for skip
    __shared__ float wsk[136];
    int tid = threadIdx.x;
    int rowlen = 32 * Tin;
    for (int i = tid; i < rowlen; i += nthr) sx[i] = S[(size_t)bn * rowlen + i];
    for (int i = tid; i < 1024; i += nthr) { sfw[i] = fw[i]; sgw[i] = gw[i]; }
    for (int i = tid; i < 32; i += nthr)   { sfb[i] = fb[i]; sgb[i] = gb[i]; }
    for (int i = tid; i < 128; i += nthr)  wsk[i] = skw[i];
    if (tid < 8) wsk[128 + tid] = skb[tid];
    __syncthreads();
    int s = tid / (16 * Ti);
    int r = tid % (16 * Ti);
    int o = r / Ti, t = r % Ti;
    float f = sfb[s * 16 + o], g = sgb[s * 16 + o];
    int base = s * 16 * Tin + t;
#pragma unroll
    for (int c = 0; c < 16; c++) {
        float xa = sx[base + c * Tin];
        float xb2 = sx[base + c * Tin + d];
        int wi = ((s * 16 + o) * 16 + c) * 2;
        f += sfw[wi] * xa + sfw[wi + 1] * xb2;
        g += sgw[wi] * xa + sgw[wi + 1] * xb2;
    }
    float val = tanhf(f) * (1.f / (1.f + expf(-g)));
    G[(size_t)bn * nthr + tid] = val;
    if (s == 0) sG0[r] = val;
    __syncthreads();
    // skip: 8*Ti outputs from stream-0 gated
    if (tid < 8 * Ti) {
        int c = tid / Ti, tt = tid % Ti;
        float acc = wsk[128 + c];
#pragma unroll
        for (int k = 0; k < 16; k++) acc += wsk[c * 16 + k] * sG0[k * Ti + tt];
        SK[(size_t)bn * 304 + skoff + tid] = acc;
    }
}

// ---------------- tensor-core batched graph GEMM (bf16, m16n8k16) ----------------
__device__ __forceinline__ uint32_t pk2(float lo, float hi) {
    uint32_t u;
    asm("cvt.rn.bf16x2.f32 %0, %1, %2;" : "=r"(u) : "f"(hi), "f"(lo));
    return u;
}

__device__ __forceinline__ void mma_bf16(float* c, const uint32_t* a, const uint32_t* b) {
    asm volatile(
        "mma.sync.aligned.m16n8k16.row.col.f32.bf16.bf16.f32 "
        "{%0,%1,%2,%3}, {%4,%5,%6,%7}, {%8,%9}, {%0,%1,%2,%3};"
        : "+f"(c[0]), "+f"(c[1]), "+f"(c[2]), "+f"(c[3])
        : "r"(a[0]), "r"(a[1]), "r"(a[2]), "r"(a[3]), "r"(b[0]), "r"(b[1]));
}

#define GP 136   // smem row pad (u32): %32==8 -> conflict-free fragment loads

__global__ __launch_bounds__(256) void k_gemm_tc(
        const float* __restrict__ Ab, const float* __restrict__ Xb,
        float* __restrict__ Yb, int L,
        int xstride, int xoff, int ystride, int yoff) {
    int b = blockIdx.z;
    const float* A = Ab + (size_t)b * NNODE * NNODE;
    const float* X = Xb + (size_t)b * NNODE * xstride + xoff;
    float* Y = Yb + (size_t)b * NNODE * ystride + yoff;
    int row0 = blockIdx.y * 128, col0 = blockIdx.x * 128;

    __shared__ uint32_t As[8][GP];   // [kpair][m]
    __shared__ uint32_t Bs[8][GP];   // [kpair][n]

    int tid = threadIdx.x;
    int lane = tid & 31, wid = tid >> 5;
    int warpM = wid >> 1, warpN = wid & 1;   // 4x2 warps -> 32x64 warp tile
    int g = lane >> 2, r = lane & 3;

    int aKP = tid & 7, aM = tid >> 3;        // m = aM + i*32
    int bN = tid & 127, bKP = tid >> 7;      // kpair = bKP + i*2
    bool bColOK = (col0 + bN) < L;

    float2 ra[4];
    float rb[8];
    float acc[2][8][4];
#pragma unroll
    for (int mi = 0; mi < 2; mi++)
#pragma unroll
        for (int ni = 0; ni < 8; ni++)
#pragma unroll
            for (int q = 0; q < 4; q++) acc[mi][ni][q] = 0.f;

    // ---- load tile k0 = 0 into registers ----
#pragma unroll
    for (int i = 0; i < 4; i++) {
        int m = row0 + aM + i * 32, gk = 2 * aKP;
        if (m < NNODE && gk + 1 < NNODE)
            ra[i] = *(const float2*)(A + (size_t)m * NNODE + gk);
        else {
            ra[i].x = (m < NNODE && gk < NNODE) ? A[(size_t)m * NNODE + gk] : 0.f;
            ra[i].y = 0.f;
        }
    }
#pragma unroll
    for (int i = 0; i < 4; i++) {
        int kp = bKP + i * 2, gk = 2 * kp;
        rb[2 * i]     = (gk < NNODE && bColOK)     ? X[(size_t)gk * xstride + col0 + bN] : 0.f;
        rb[2 * i + 1] = (gk + 1 < NNODE && bColOK) ? X[(size_t)(gk + 1) * xstride + col0 + bN] : 0.f;
    }
#pragma unroll
    for (int i = 0; i < 4; i++) As[aKP][aM + i * 32] = pk2(ra[i].x, ra[i].y);
#pragma unroll
    for (int i = 0; i < 4; i++) Bs[bKP + i * 2][bN] = pk2(rb[2 * i], rb[2 * i + 1]);
    __syncthreads();

    for (int k0 = 0; k0 < NNODE; k0 += 16) {
        bool nxt = (k0 + 16) < NNODE;
        if (nxt) {
            int k1 = k0 + 16;
#pragma unroll
            for (int i = 0; i < 4; i++) {
                int m = row0 + aM + i * 32, gk = k1 + 2 * aKP;
                if (m < NNODE && gk + 1 < NNODE)
                    ra[i] = *(const float2*)(A + (size_t)m * NNODE + gk);
                else {
                    ra[i].x = (m < NNODE && gk < NNODE) ? A[(size_t)m * NNODE + gk] : 0.f;
                    ra[i].y = 0.f;
                }
            }
#pragma unroll
            for (int i = 0; i < 4; i++) {
                int kp = bKP + i * 2, gk = k1 + 2 * kp;
                rb[2 * i]     = (gk < NNODE && bColOK)     ? X[(size_t)gk * xstride + col0 + bN] : 0.f;
                rb[2 * i + 1] = (gk + 1 < NNODE && bColOK) ? X[(size_t)(gk + 1) * xstride + col0 + bN] : 0.f;
            }
        }
        // compute from smem: one m16n8k16 covers the whole 16-k tile
        {
            uint32_t af[2][4], bf[8][2];
#pragma unroll
            for (int mi = 0; mi < 2; mi++) {
                int mb = warpM * 32 + mi * 16;
                af[mi][0] = As[r][mb + g];
                af[mi][1] = As[r][mb + g + 8];
                af[mi][2] = As[r + 4][mb + g];
                af[mi][3] = As[r + 4][mb + g + 8];
            }
#pragma unroll
            for (int ni = 0; ni < 8; ni++) {
                int nb = warpN * 64 + ni * 8;
                bf[ni][0] = Bs[r][nb + g];
                bf[ni][1] = Bs[r + 4][nb + g];
            }
#pragma unroll
            for (int mi = 0; mi < 2; mi++)
#pragma unroll
                for (int ni = 0; ni < 8; ni++)
                    mma_bf16(acc[mi][ni], af[mi], bf[ni]);
        }
        __syncthreads();
        if (nxt) {
#pragma unroll
            for (int i = 0; i < 4; i++) As[aKP][aM + i * 32] = pk2(ra[i].x, ra[i].y);
#pragma unroll
            for (int i = 0; i < 4; i++) Bs[bKP + i * 2][bN] = pk2(rb[2 * i], rb[2 * i + 1]);
            __syncthreads();
        }
    }

    // epilogue
#pragma unroll
    for (int mi = 0; mi < 2; mi++) {
#pragma unroll
        for (int ni = 0; ni < 8; ni++) {
            int row = row0 + warpM * 32 + mi * 16 + g;
            int col = col0 + warpN * 64 + ni * 8 + 2 * r;
            if (row < NNODE) {
                if (col < L)     Y[(size_t)row * ystride + col]     = acc[mi][ni][0];
                if (col + 1 < L) Y[(size_t)row * ystride + col + 1] = acc[mi][ni][1];
            }
            if (row + 8 < NNODE) {
                if (col < L)     Y[(size_t)(row + 8) * ystride + col]     = acc[mi][ni][2];
                if (col + 1 < L) Y[(size_t)(row + 8) * ystride + col + 1] = acc[mi][ni][3];
            }
        }
    }
}

// ---------------- gconv pointwise: g = W*[G, Y1, Y2] + b ----------------
__global__ void k_g01(const float* __restrict__ G, const float* __restrict__ Y1,
                      const float* __restrict__ Y2, const float* __restrict__ gw,
                      const float* __restrict__ gb, float* __restrict__ G01, int Ti) {
    int bn = blockIdx.x;
    int nthr = 32 * Ti;
    __shared__ float sg[512], sy1[512], sy2[512], sw_[1536], sb_[32];
    size_t base = (size_t)bn * nthr;
    int tid = threadIdx.x;
    sg[tid] = G[base + tid]; sy1[tid] = Y1[base + tid]; sy2[tid] = Y2[base + tid];
    for (int i = tid; i < 1536; i += nthr) sw_[i] = gw[i];
    if (tid < 32) sb_[tid] = gb[tid];
    __syncthreads();
    int s = tid / (16 * Ti);
    int r = tid % (16 * Ti);
    int o = r / Ti, t = r % Ti;
    float acc = sb_[s * 16 + o];
    const float* w = sw_ + (s * 16 + o) * 48;
    int cb = s * 16 * Ti + t;
#pragma unroll
    for (int c = 0; c < 16; c++)
        acc += w[c] * sg[cb + c * Ti] + w[16 + c] * sy1[cb + c * Ti] + w[32 + c] * sy2[cb + c * Ti];
    G01[base + tid] = acc;
}

// ---------------- residual/state update ----------------
__global__ void k_update(const float* __restrict__ Sin, const float* __restrict__ G01,
                         const float* __restrict__ Z1, const float* __restrict__ Z2,
                         const float* __restrict__ gaw, const float* __restrict__ gab,
                         float* __restrict__ Sout, int d, int Tin, int Ti) {
    int bn = blockIdx.x;
    int tid = threadIdx.x;
    int nthr = 32 * Ti;
    int rl = 16 * Ti;
    __shared__ float sg1[256], sz1[256], sz2[256], sw_[768], sb_[16];
    size_t gbase = (size_t)bn * nthr;
    for (int i = tid; i < rl; i += nthr) {
        sg1[i] = G01[gbase + rl + i];
        sz1[i] = Z1[(size_t)bn * rl + i];
        sz2[i] = Z2[(size_t)bn * rl + i];
    }
    for (int i = tid; i < 768; i += nthr) sw_[i] = gaw[i];
    if (tid < 16) sb_[tid] = gab[tid];
    __syncthreads();
    int s = tid / rl;
    int r = tid % rl;
    int c = r / Ti, t = r % Ti;
    float out;
    if (s == 0) {
        float xap = sb_[c];
        const float* w = sw_ + c * 48;
#pragma unroll
        for (int k = 0; k < 16; k++)
            xap += w[k] * sg1[k * Ti + t] + w[16 + k] * sz1[k * Ti + t] + w[32 + k] * sz2[k * Ti + t];
        float g0 = G01[gbase + c * Ti + t];
        float r0 = Sin[(size_t)bn * (32 * Tin) + c * Tin + (t + d)];
        out = (2.f * g0 + xap + r0) * BN_SCALE;
    } else {
        float r1 = Sin[(size_t)bn * (32 * Tin) + (16 + c) * Tin + (t + d)];
        out = r1 * BN_SCALE;
    }
    Sout[gbase + tid] = out;
}

// ---------------- end convs ----------------
__global__ void k_end(const float* __restrict__ SK, const float* __restrict__ e1w,
                      const float* __restrict__ e1b, const float* __restrict__ e2w,
                      const float* __restrict__ e2b, float* __restrict__ out) {
    int warp = threadIdx.x >> 5, lane = threadIdx.x & 31;
    int bn = blockIdx.x * 4 + warp;
    if (bn >= BB * NNODE) return;
    int b = bn / NNODE, n = bn % NNODE;
    const float* sk = SK + (size_t)bn * 304;
    float acc[16];
#pragma unroll
    for (int o = 0; o < 16; o++) acc[o] = 0.f;
    for (int k = lane; k < 304; k += 32) {
        float v = fmaxf(sk[k], 0.f);
#pragma unroll
        for (int o = 0; o < 16; o++) acc[o] += e1w[o * 304 + k] * v;
    }
#pragma unroll
    for (int o = 0; o < 16; o++) {
#pragma unroll
        for (int off = 16; off > 0; off >>= 1)
            acc[o] += __shfl_xor_sync(0xffffffff, acc[o], off);
    }
    if (lane == 0) {
        float e1[16];
#pragma unroll
        for (int o = 0; o < 16; o++) e1[o] = fmaxf(acc[o] + e1b[o], 0.f);
#pragma unroll
        for (int o2 = 0; o2 < 3; o2++) {
            float s = e2b[o2];
#pragma unroll
            for (int o = 0; o < 16; o++) s += e2w[o2 * 16 + o] * e1[o];
            out[((size_t)b * 3 + o2) * NNODE + n] = s;
        }
    }
}

// ---------------- host orchestration ----------------
extern "C" void kernel_launch(void* const* d_in, const int* in_sizes, int n_in,
                              void* d_out, int out_size) {
    const float* inputs  = (const float*)d_in[0];
    const int*   ind     = (const int*)  d_in[1];
    const float* start_w = (const float*)d_in[2];
    const float* start_b = (const float*)d_in[3];
    const float* p1      = (const float*)d_in[4];
    const float* p2      = (const float*)d_in[5];
    const float* p3      = (const float*)d_in[6];
    const float* pk      = (const float*)d_in[7];
    const float* a2p1    = (const float*)d_in[8];
    const float* a2p2    = (const float*)d_in[9];
    const float* a2p3    = (const float*)d_in[10];
    const float* a2pk    = (const float*)d_in[11];
    const float* filt_w  = (const float*)d_in[12];
    const float* filt_b  = (const float*)d_in[13];
    const float* gate_w  = (const float*)d_in[14];
    const float* gate_b  = (const float*)d_in[15];
    const float* gconv_w = (const float*)d_in[16];
    const float* gconv_b = (const float*)d_in[17];
    const float* ga_w    = (const float*)d_in[18];
    const float* ga_b    = (const float*)d_in[19];
    const float* skip_w  = (const float*)d_in[20];
    const float* skip_b  = (const float*)d_in[21];
    const float* end1_w  = (const float*)d_in[22];
    const float* end1_b  = (const float*)d_in[23];
    const float* end2_w  = (const float*)d_in[24];
    const float* end2_b  = (const float*)d_in[25];
    float* out = (float*)d_out;

    float *adp, *adp2, *T1, *T2, *M1, *M2, *S0, *S1, *G, *Y1, *Y2, *G01, *Z1, *Z2, *SK;
    cudaGetSymbolAddress((void**)&adp,  g_adp);
    cudaGetSymbolAddress((void**)&adp2, g_adp2);
    cudaGetSymbolAddress((void**)&T1,   g_T1);
    cudaGetSymbolAddress((void**)&T2,   g_T2);
    cudaGetSymbolAddress((void**)&M1,   g_M1);
    cudaGetSymbolAddress((void**)&M2,   g_M2);
    cudaGetSymbolAddress((void**)&S0,   g_S0);
    cudaGetSymbolAddress((void**)&S1,   g_S1);
    cudaGetSymbolAddress((void**)&G,    g_G);
    cudaGetSymbolAddress((void**)&Y1,   g_Y1);
    cudaGetSymbolAddress((void**)&Y2,   g_Y2);
    cudaGetSymbolAddress((void**)&G01,  g_G01);
    cudaGetSymbolAddress((void**)&Z1,   g_Z1);
    cudaGetSymbolAddress((void**)&Z2,   g_Z2);
    cudaGetSymbolAddress((void**)&SK,   g_SK);

    int nM = BB * NNODE * DIMS;
    const int dil[4]     = {1, 2, 4, 8};
    const int skipoff[4] = {184, 80, 8, 0};

    // --- ordered so launch #5 (ncu -s 5 -c 1) is the big layer-0 Y1 graph GEMM ---
    k_T<<<BB, 256>>>(p1, pk, ind, T1);                                   // 0
    k_M<<<(nM + 255) / 256, 256>>>(p2, T1, M1);                          // 1
    k_adp<<<BB * NNODE, 256>>>(M1, p3, adp);                             // 2
    k_start<<<BB * NNODE, 512>>>(inputs, start_w, start_b, S0);          // 3

    // layer 0 gated+skip
    {
        int d = dil[0], Tin = 16, Ti = Tin - d;          // Ti = 15
        k_gated<<<BB * NNODE, 32 * Ti>>>(S0, G,
            filt_w, filt_b, gate_w, gate_b,
            skip_w, skip_b, SK, skipoff[0], d, Tin, Ti); // 4
        int L = 32 * Ti;
        dim3 grid((L + 127) / 128, (NNODE + 127) / 128, BB);
        k_gemm_tc<<<grid, 256>>>(adp, G, Y1, L, L, 0, L, 0);             // 5 <- profiled
        // second adjacency (independent; fills the gap)
        k_T<<<BB, 256>>>(a2p1, a2pk, ind, T2);                           // 6
        k_M<<<(nM + 255) / 256, 256>>>(a2p2, T2, M2);                    // 7
        k_adp<<<BB * NNODE, 256>>>(M2, a2p3, adp2);                      // 8
        k_gemm_tc<<<grid, 256>>>(adp, Y1, Y2, L, L, 0, L, 0);            // 9
        k_g01<<<BB * NNODE, 32 * Ti>>>(G, Y1, Y2, gconv_w, gconv_b, G01, Ti);
        int L2 = 16 * Ti;
        dim3 grid2((L2 + 127) / 128, (NNODE + 127) / 128, BB);
        k_gemm_tc<<<grid2, 256>>>(adp2, G01, Z1, L2, 32 * Ti, 16 * Ti, L2, 0);
        k_gemm_tc<<<grid2, 256>>>(adp2, Z1, Z2, L2, L2, 0, L2, 0);
        k_update<<<BB * NNODE, 32 * Ti>>>(S0, G01, Z1, Z2, ga_w, ga_b, S1, d, Tin, Ti);
    }

    // layers 1..3
    float* Sin = S1;
    float* Sout = S0;
    int Tin = 15;
    for (int i = 1; i < 4; i++) {
        int d = dil[i];
        int Ti = Tin - d;
        k_gated<<<BB * NNODE, 32 * Ti>>>(Sin, G,
            filt_w + i * 1024, filt_b + i * 32,
            gate_w + i * 1024, gate_b + i * 32,
            skip_w + i * 128, skip_b + i * 8, SK, skipoff[i], d, Tin, Ti);
        if (i < 3) {
            int L = 32 * Ti;
            dim3 grid((L + 127) / 128, (NNODE + 127) / 128, BB);
            k_gemm_tc<<<grid, 256>>>(adp, G,  Y1, L, L, 0, L, 0);
            k_gemm_tc<<<grid, 256>>>(adp, Y1, Y2, L, L, 0, L, 0);
            k_g01<<<BB * NNODE, 32 * Ti>>>(G, Y1, Y2,
                gconv_w + i * 1536, gconv_b + i * 32, G01, Ti);
            int L2 = 16 * Ti;
            dim3 grid2((L2 + 127) / 128, (NNODE + 127) / 128, BB);
            k_gemm_tc<<<grid2, 256>>>(adp2, G01, Z1, L2, 32 * Ti, 16 * Ti, L2, 0);
            k_gemm_tc<<<grid2, 256>>>(adp2, Z1,  Z2, L2, L2, 0, L2, 0);
            k_update<<<BB * NNODE, 32 * Ti>>>(Sin, G01, Z1, Z2,
                ga_w + i * 768, ga_b + i * 16, Sout, d, Tin, Ti);
            float* tmp = Sin; Sin = Sout; Sout = tmp;
        }
        Tin = Ti;
    }

    k_end<<<(BB * NNODE + 3) / 4, 128>>>(SK, end1_w, end1_b, end2_w, end2_b, out);
}

// round 5
// speedup vs baseline: 1.6717x; 1.0105x over previous
#include <cuda_runtime.h>
#include <math.h>
#include <stdint.h>

#define BB 64
#define NNODE 500
#define DIMS 40
#define BN_SCALE 0.99999500003749968750f  // 1/sqrt(1+1e-5)

// ---------------- scratch (device globals; no allocation allowed) ----------------
__device__ uint32_t g_adp_bf [BB * 512 * 256];   // bf16x2 pairs, [b][row<=512][256 kpairs]
__device__ uint32_t g_adp2_bf[BB * 512 * 256];
__device__ float g_T1[BB * DIMS * DIMS];
__device__ float g_T2[BB * DIMS * DIMS];
__device__ float g_S0 [BB * NNODE * 512];
__device__ float g_S1 [BB * NNODE * 512];
__device__ float g_G  [BB * NNODE * 512];
__device__ float g_Y1 [BB * NNODE * 512];
__device__ float g_Y2 [BB * NNODE * 512];
__device__ float g_G01[BB * NNODE * 512];
__device__ float g_Z1 [BB * NNODE * 256];
__device__ float g_Z2 [BB * NNODE * 256];
__device__ float g_SK [BB * NNODE * 304];

__device__ __forceinline__ uint32_t pk2(float lo, float hi) {
    uint32_t u;
    asm("cvt.rn.bf16x2.f32 %0, %1, %2;" : "=r"(u) : "f"(hi), "f"(lo));
    return u;
}

// ---------------- T[b,j,k] = sum_i p1[ind[b],i] * pk[i,j,k] ----------------
__global__ void k_T(const float* __restrict__ p1, const float* __restrict__ pk,
                    const int* __restrict__ ind, float* __restrict__ Tout) {
    int b = blockIdx.x;
    __shared__ float te[DIMS];
    int day = ind[b];
    if (threadIdx.x < DIMS) te[threadIdx.x] = p1[day * DIMS + threadIdx.x];
    __syncthreads();
    for (int jk = threadIdx.x; jk < DIMS * DIMS; jk += blockDim.x) {
        float s = 0.f;
#pragma unroll
        for (int i = 0; i < DIMS; i++) s += te[i] * pk[i * DIMS * DIMS + jk];
        Tout[b * DIMS * DIMS + jk] = s;
    }
}

// ---------------- fused M + softmax-adjacency, bf16 packed output ----------------
// per block (b,w): M[k] = sum_j p2[w,j] T[b,j,k]; A[w,v] = softmax_v relu(p3[v,:]·M)
__global__ void k_adp(const float* __restrict__ p2, const float* __restrict__ p3,
                      const float* __restrict__ T, uint32_t* __restrict__ Abf) {
    int bw = blockIdx.x;
    int b = bw / NNODE, w = bw % NNODE;
    __shared__ float Ts[DIMS * DIMS];
    __shared__ float p2s[DIMS];
    __shared__ float mrow[DIMS];
    __shared__ float vals[512];
    __shared__ float red[256];
    int tid = threadIdx.x;
    for (int i = tid; i < DIMS * DIMS; i += 256) Ts[i] = T[b * DIMS * DIMS + i];
    if (tid < DIMS) p2s[tid] = p2[w * DIMS + tid];
    if (tid < 12) vals[500 + tid] = 0.f;
    __syncthreads();
    if (tid < DIMS) {
        float s = 0.f;
#pragma unroll
        for (int j = 0; j < DIMS; j++) s += p2s[j] * Ts[j * DIMS + tid];
        mrow[tid] = s;
    }
    __syncthreads();
    for (int v = tid; v < NNODE; v += 256) {
        float s = 0.f;
#pragma unroll
        for (int k = 0; k < DIMS; k++) s += p3[v * DIMS + k] * mrow[k];
        vals[v] = fmaxf(s, 0.f);
    }
    __syncthreads();
    float m = 0.f;
    for (int v = tid; v < NNODE; v += 256) m = fmaxf(m, vals[v]);
    red[tid] = m; __syncthreads();
    for (int s2 = 128; s2 > 0; s2 >>= 1) {
        if (tid < s2) red[tid] = fmaxf(red[tid], red[tid + s2]);
        __syncthreads();
    }
    m = red[0];
    __syncthreads();
    float sum = 0.f;
    for (int v = tid; v < NNODE; v += 256) {
        float e = expf(vals[v] - m);
        vals[v] = e; sum += e;
    }
    red[tid] = sum; __syncthreads();
    for (int s2 = 128; s2 > 0; s2 >>= 1) {
        if (tid < s2) red[tid] += red[tid + s2];
        __syncthreads();
    }
    float inv = 1.f / red[0];
    __syncthreads();
    uint32_t* Arow = Abf + ((size_t)b * 512 + w) * 256;
    if (tid < 256) Arow[tid] = pk2(vals[2 * tid] * inv, vals[2 * tid + 1] * inv);
}

// ---------------- layer-0: fused start embedding + gated conv + skip ----------------
__global__ void k_gated0(const float* __restrict__ inp,
                         const float* __restrict__ sw, const float* __restrict__ sb,
                         float* __restrict__ S0, float* __restrict__ G,
                         const float* __restrict__ fw, const float* __restrict__ fb,
                         const float* __restrict__ gw, const float* __restrict__ gb,
                         const float* __restrict__ skw, const float* __restrict__ skb,
                         float* __restrict__ SK, int skoff) {
    const int d = 1, Tin = 16, Ti = 15, nthr = 32 * Ti;
    int bn = blockIdx.x;
    int b = bn / NNODE, n = bn % NNODE;
    __shared__ float xraw[32];           // [s][t]
    __shared__ float sx[512];
    __shared__ float sfw[1024], sgw[1024], sfb[32], sgb[32];
    __shared__ float sG0[256];
    __shared__ float wsk[136];
    int tid = threadIdx.x;
    if (tid < 32) {
        int t = tid & 15, s = tid >> 4;
        xraw[s * 16 + t] = inp[(((size_t)b * 16 + t) * NNODE + n) * 2 + s];
    }
    for (int i = tid; i < 1024; i += nthr) { sfw[i] = fw[i]; sgw[i] = gw[i]; }
    for (int i = tid; i < 32; i += nthr)   { sfb[i] = fb[i]; sgb[i] = gb[i]; }
    for (int i = tid; i < 128; i += nthr)  wsk[i] = skw[i];
    if (tid < 8) wsk[128 + tid] = skb[tid];
    __syncthreads();
    for (int i = tid; i < 512; i += nthr) {
        int t = i & 15, sc = i >> 4;          // sc = s*16+c
        int s = sc >> 4;
        float v = xraw[s * 16 + t] * sw[sc] + sb[sc];
        sx[i] = v;
        S0[(size_t)bn * 512 + i] = v;
    }
    __syncthreads();
    int s = tid / (16 * Ti);
    int r = tid % (16 * Ti);
    int o = r / Ti, t = r % Ti;
    float f = sfb[s * 16 + o], g = sgb[s * 16 + o];
    int base = s * 16 * Tin + t;
#pragma unroll
    for (int c = 0; c < 16; c++) {
        float xa = sx[base + c * Tin];
        float xb2 = sx[base + c * Tin + d];
        int wi = ((s * 16 + o) * 16 + c) * 2;
        f += sfw[wi] * xa + sfw[wi + 1] * xb2;
        g += sgw[wi] * xa + sgw[wi + 1] * xb2;
    }
    float val = tanhf(f) * (1.f / (1.f + expf(-g)));
    G[(size_t)bn * nthr + tid] = val;
    if (s == 0) sG0[r] = val;
    __syncthreads();
    if (tid < 8 * Ti) {
        int c = tid / Ti, tt = tid % Ti;
        float acc = wsk[128 + c];
#pragma unroll
        for (int k = 0; k < 16; k++) acc += wsk[c * 16 + k] * sG0[k * Ti + tt];
        SK[(size_t)bn * 304 + skoff + tid] = acc;
    }
}

// ---------------- layers 1-3: gated conv + skip ----------------
__global__ void k_gated(const float* __restrict__ S, float* __restrict__ G,
                        const float* __restrict__ fw, const float* __restrict__ fb,
                        const float* __restrict__ gw, const float* __restrict__ gb,
                        const float* __restrict__ skw, const float* __restrict__ skb,
                        float* __restrict__ SK, int skoff,
                        int d, int Tin, int Ti) {
    int bn = blockIdx.x;
    int nthr = 32 * Ti;
    __shared__ float sx[512];
    __shared__ float sfw[1024], sgw[1024], sfb[32], sgb[32];
    __shared__ float sG0[256];
    __shared__ float wsk[136];
    int tid = threadIdx.x;
    int rowlen = 32 * Tin;
    for (int i = tid; i < rowlen; i += nthr) sx[i] = S[(size_t)bn * rowlen + i];
    for (int i = tid; i < 1024; i += nthr) { sfw[i] = fw[i]; sgw[i] = gw[i]; }
    for (int i = tid; i < 32; i += nthr)   { sfb[i] = fb[i]; sgb[i] = gb[i]; }
    for (int i = tid; i < 128; i += nthr)  wsk[i] = skw[i];
    if (tid < 8) wsk[128 + tid] = skb[tid];
    __syncthreads();
    int s = tid / (16 * Ti);
    int r = tid % (16 * Ti);
    int o = r / Ti, t = r % Ti;
    float f = sfb[s * 16 + o], g = sgb[s * 16 + o];
    int base = s * 16 * Tin + t;
#pragma unroll
    for (int c = 0; c < 16; c++) {
        float xa = sx[base + c * Tin];
        float xb2 = sx[base + c * Tin + d];
        int wi = ((s * 16 + o) * 16 + c) * 2;
        f += sfw[wi] * xa + sfw[wi + 1] * xb2;
        g += sgw[wi] * xa + sgw[wi + 1] * xb2;
    }
    float val = tanhf(f) * (1.f / (1.f + expf(-g)));
    G[(size_t)bn * nthr + tid] = val;
    if (s == 0) sG0[r] = val;
    __syncthreads();
    if (tid < 8 * Ti) {
        int c = tid / Ti, tt = tid % Ti;
        float acc = wsk[128 + c];
#pragma unroll
        for (int k = 0; k < 16; k++) acc += wsk[c * 16 + k] * sG0[k * Ti + tt];
        SK[(size_t)bn * 304 + skoff + tid] = acc;
    }
}

// ---------------- tensor-core batched graph GEMM (bf16 A packed, k-step 32) ------
__device__ __forceinline__ void mma_bf16(float* c, const uint32_t* a, const uint32_t* b) {
    asm volatile(
        "mma.sync.aligned.m16n8k16.row.col.f32.bf16.bf16.f32 "
        "{%0,%1,%2,%3}, {%4,%5,%6,%7}, {%8,%9}, {%0,%1,%2,%3};"
        : "+f"(c[0]), "+f"(c[1]), "+f"(c[2]), "+f"(c[3])
        : "r"(a[0]), "r"(a[1]), "r"(a[2]), "r"(a[3]), "r"(b[0]), "r"(b[1]));
}

#define GP 136

__global__ __launch_bounds__(256) void k_gemm_tc(
        const uint32_t* __restrict__ Abf, const float* __restrict__ Xb,
        float* __restrict__ Yb, int L,
        int xstride, int xoff, int ystride, int yoff) {
    int b = blockIdx.z;
    const uint32_t* A = Abf + (size_t)b * 512 * 256;
    const float* X = Xb + (size_t)b * NNODE * xstride + xoff;
    float* Y = Yb + (size_t)b * NNODE * ystride + yoff;
    int row0 = blockIdx.y * 128, col0 = blockIdx.x * 128;

    __shared__ uint32_t As[16][GP];   // [kpair][m]
    __shared__ uint32_t Bs[16][GP];   // [kpair][n]

    int tid = threadIdx.x;
    int lane = tid & 31, wid = tid >> 5;
    int warpM = wid >> 1, warpN = wid & 1;   // 4x2 warps -> 32x64 warp tile
    int g = lane >> 2, r = lane & 3;

    int aKP = tid & 7, aM = tid >> 3;        // m = aM + i*32
    int bN = tid & 127, bKP = tid >> 7;      // kpair = bKP + 2i
    bool colOK = (col0 + bN) < L;

    uint32_t ra[8];
    float rb[16];
    float acc[2][8][4];
#pragma unroll
    for (int mi = 0; mi < 2; mi++)
#pragma unroll
        for (int ni = 0; ni < 8; ni++)
#pragma unroll
            for (int q = 0; q < 4; q++) acc[mi][ni][q] = 0.f;

#define LOAD_A(K0) do {                                               \
    int kb = (K0) >> 1;                                               \
    _Pragma("unroll")                                                 \
    for (int i = 0; i < 4; i++) {                                     \
        int m = row0 + aM + i * 32;                                   \
        ra[i]     = (m < NNODE) ? A[(size_t)m * 256 + kb + aKP]     : 0u; \
        ra[i + 4] = (m < NNODE) ? A[(size_t)m * 256 + kb + 8 + aKP] : 0u; \
    } } while (0)

#define LOAD_B(K0) do {                                               \
    _Pragma("unroll")                                                 \
    for (int i = 0; i < 8; i++) {                                     \
        int gk = (K0) + 2 * (bKP + 2 * i);                            \
        rb[2*i]   = (gk < NNODE && colOK)     ? X[(size_t)gk * xstride + col0 + bN] : 0.f; \
        rb[2*i+1] = (gk + 1 < NNODE && colOK) ? X[(size_t)(gk + 1) * xstride + col0 + bN] : 0.f; \
    } } while (0)

#define STORE_SM() do {                                               \
    _Pragma("unroll")                                                 \
    for (int i = 0; i < 4; i++) {                                     \
        As[aKP][aM + 32 * i]     = ra[i];                             \
        As[aKP + 8][aM + 32 * i] = ra[i + 4];                         \
    }                                                                 \
    _Pragma("unroll")                                                 \
    for (int i = 0; i < 8; i++)                                       \
        Bs[bKP + 2 * i][bN] = pk2(rb[2*i], rb[2*i+1]);                \
    } while (0)

    LOAD_A(0); LOAD_B(0); STORE_SM();
    __syncthreads();

    for (int k0 = 0; k0 < NNODE; k0 += 32) {
        bool nxt = (k0 + 32) < NNODE;
        if (nxt) { LOAD_A(k0 + 32); LOAD_B(k0 + 32); }
#pragma unroll
        for (int half = 0; half < 2; half++) {
            int kb = half * 8;
            uint32_t af[2][4], bf[8][2];
#pragma unroll
            for (int mi = 0; mi < 2; mi++) {
                int mb = warpM * 32 + mi * 16;
                af[mi][0] = As[kb + r][mb + g];
                af[mi][1] = As[kb + r][mb + g + 8];
                af[mi][2] = As[kb + r + 4][mb + g];
                af[mi][3] = As[kb + r + 4][mb + g + 8];
            }
#pragma unroll
            for (int ni = 0; ni < 8; ni++) {
                int nb = warpN * 64 + ni * 8;
                bf[ni][0] = Bs[kb + r][nb + g];
                bf[ni][1] = Bs[kb + r + 4][nb + g];
            }
#pragma unroll
            for (int mi = 0; mi < 2; mi++)
#pragma unroll
                for (int ni = 0; ni < 8; ni++)
                    mma_bf16(acc[mi][ni], af[mi], bf[ni]);
        }
        __syncthreads();
        if (nxt) { STORE_SM(); __syncthreads(); }
    }

#pragma unroll
    for (int mi = 0; mi < 2; mi++) {
#pragma unroll
        for (int ni = 0; ni < 8; ni++) {
            int row = row0 + warpM * 32 + mi * 16 + g;
            int col = col0 + warpN * 64 + ni * 8 + 2 * r;
            if (row < NNODE) {
                if (col < L)     Y[(size_t)row * ystride + col]     = acc[mi][ni][0];
                if (col + 1 < L) Y[(size_t)row * ystride + col + 1] = acc[mi][ni][1];
            }
            if (row + 8 < NNODE) {
                if (col < L)     Y[(size_t)(row + 8) * ystride + col]     = acc[mi][ni][2];
                if (col + 1 < L) Y[(size_t)(row + 8) * ystride + col + 1] = acc[mi][ni][3];
            }
        }
    }
}

// ---------------- gconv pointwise: g = W*[G, Y1, Y2] + b ----------------
__global__ void k_g01(const float* __restrict__ G, const float* __restrict__ Y1,
                      const float* __restrict__ Y2, const float* __restrict__ gw,
                      const float* __restrict__ gb, float* __restrict__ G01, int Ti) {
    int bn = blockIdx.x;
    int nthr = 32 * Ti;
    __shared__ float sg[512], sy1[512], sy2[512], sw_[1536], sb_[32];
    size_t base = (size_t)bn * nthr;
    int tid = threadIdx.x;
    sg[tid] = G[base + tid]; sy1[tid] = Y1[base + tid]; sy2[tid] = Y2[base + tid];
    for (int i = tid; i < 1536; i += nthr) sw_[i] = gw[i];
    if (tid < 32) sb_[tid] = gb[tid];
    __syncthreads();
    int s = tid / (16 * Ti);
    int r = tid % (16 * Ti);
    int o = r / Ti, t = r % Ti;
    float acc = sb_[s * 16 + o];
    const float* w = sw_ + (s * 16 + o) * 48;
    int cb = s * 16 * Ti + t;
#pragma unroll
    for (int c = 0; c < 16; c++)
        acc += w[c] * sg[cb + c * Ti] + w[16 + c] * sy1[cb + c * Ti] + w[32 + c] * sy2[cb + c * Ti];
    G01[base + tid] = acc;
}

// ---------------- residual/state update ----------------
__global__ void k_update(const float* __restrict__ Sin, const float* __restrict__ G01,
                         const float* __restrict__ Z1, const float* __restrict__ Z2,
                         const float* __restrict__ gaw, const float* __restrict__ gab,
                         float* __restrict__ Sout, int d, int Tin, int Ti) {
    int bn = blockIdx.x;
    int tid = threadIdx.x;
    int nthr = 32 * Ti;
    int rl = 16 * Ti;
    __shared__ float sg1[256], sz1[256], sz2[256], sw_[768], sb_[16];
    size_t gbase = (size_t)bn * nthr;
    for (int i = tid; i < rl; i += nthr) {
        sg1[i] = G01[gbase + rl + i];
        sz1[i] = Z1[(size_t)bn * rl + i];
        sz2[i] = Z2[(size_t)bn * rl + i];
    }
    for (int i = tid; i < 768; i += nthr) sw_[i] = gaw[i];
    if (tid < 16) sb_[tid] = gab[tid];
    __syncthreads();
    int s = tid / rl;
    int r = tid % rl;
    int c = r / Ti, t = r % Ti;
    float out;
    if (s == 0) {
        float xap = sb_[c];
        const float* w = sw_ + c * 48;
#pragma unroll
        for (int k = 0; k < 16; k++)
            xap += w[k] * sg1[k * Ti + t] + w[16 + k] * sz1[k * Ti + t] + w[32 + k] * sz2[k * Ti + t];
        float g0 = G01[gbase + c * Ti + t];
        float r0 = Sin[(size_t)bn * (32 * Tin) + c * Tin + (t + d)];
        out = (2.f * g0 + xap + r0) * BN_SCALE;
    } else {
        float r1 = Sin[(size_t)bn * (32 * Tin) + (16 + c) * Tin + (t + d)];
        out = r1 * BN_SCALE;
    }
    Sout[gbase + tid] = out;
}

// ---------------- end convs ----------------
__global__ void k_end(const float* __restrict__ SK, const float* __restrict__ e1w,
                      const float* __restrict__ e1b, const float* __restrict__ e2w,
                      const float* __restrict__ e2b, float* __restrict__ out) {
    int warp = threadIdx.x >> 5, lane = threadIdx.x & 31;
    int bn = blockIdx.x * 4 + warp;
    if (bn >= BB * NNODE) return;
    int b = bn / NNODE, n = bn % NNODE;
    const float* sk = SK + (size_t)bn * 304;
    float acc[16];
#pragma unroll
    for (int o = 0; o < 16; o++) acc[o] = 0.f;
    for (int k = lane; k < 304; k += 32) {
        float v = fmaxf(sk[k], 0.f);
#pragma unroll
        for (int o = 0; o < 16; o++) acc[o] += e1w[o * 304 + k] * v;
    }
#pragma unroll
    for (int o = 0; o < 16; o++) {
#pragma unroll
        for (int off = 16; off > 0; off >>= 1)
            acc[o] += __shfl_xor_sync(0xffffffff, acc[o], off);
    }
    if (lane == 0) {
        float e1[16];
#pragma unroll
        for (int o = 0; o < 16; o++) e1[o] = fmaxf(acc[o] + e1b[o], 0.f);
#pragma unroll
        for (int o2 = 0; o2 < 3; o2++) {
            float s = e2b[o2];
#pragma unroll
            for (int o = 0; o < 16; o++) s += e2w[o2 * 16 + o] * e1[o];
            out[((size_t)b * 3 + o2) * NNODE + n] = s;
        }
    }
}

// ---------------- host orchestration ----------------
extern "C" void kernel_launch(void* const* d_in, const int* in_sizes, int n_in,
                              void* d_out, int out_size) {
    const float* inputs  = (const float*)d_in[0];
    const int*   ind     = (const int*)  d_in[1];
    const float* start_w = (const float*)d_in[2];
    const float* start_b = (const float*)d_in[3];
    const float* p1      = (const float*)d_in[4];
    const float* p2      = (const float*)d_in[5];
    const float* p3      = (const float*)d_in[6];
    const float* pk      = (const float*)d_in[7];
    const float* a2p1    = (const float*)d_in[8];
    const float* a2p2    = (const float*)d_in[9];
    const float* a2p3    = (const float*)d_in[10];
    const float* a2pk    = (const float*)d_in[11];
    const float* filt_w  = (const float*)d_in[12];
    const float* filt_b  = (const float*)d_in[13];
    const float* gate_w  = (const float*)d_in[14];
    const float* gate_b  = (const float*)d_in[15];
    const float* gconv_w = (const float*)d_in[16];
    const float* gconv_b = (const float*)d_in[17];
    const float* ga_w    = (const float*)d_in[18];
    const float* ga_b    = (const float*)d_in[19];
    const float* skip_w  = (const float*)d_in[20];
    const float* skip_b  = (const float*)d_in[21];
    const float* end1_w  = (const float*)d_in[22];
    const float* end1_b  = (const float*)d_in[23];
    const float* end2_w  = (const float*)d_in[24];
    const float* end2_b  = (const float*)d_in[25];
    float* out = (float*)d_out;

    uint32_t *adp, *adp2;
    float *T1, *T2, *S0, *S1, *G, *Y1, *Y2, *G01, *Z1, *Z2, *SK;
    cudaGetSymbolAddress((void**)&adp,  g_adp_bf);
    cudaGetSymbolAddress((void**)&adp2, g_adp2_bf);
    cudaGetSymbolAddress((void**)&T1,   g_T1);
    cudaGetSymbolAddress((void**)&T2,   g_T2);
    cudaGetSymbolAddress((void**)&S0,   g_S0);
    cudaGetSymbolAddress((void**)&S1,   g_S1);
    cudaGetSymbolAddress((void**)&G,    g_G);
    cudaGetSymbolAddress((void**)&Y1,   g_Y1);
    cudaGetSymbolAddress((void**)&Y2,   g_Y2);
    cudaGetSymbolAddress((void**)&G01,  g_G01);
    cudaGetSymbolAddress((void**)&Z1,   g_Z1);
    cudaGetSymbolAddress((void**)&Z2,   g_Z2);
    cudaGetSymbolAddress((void**)&SK,   g_SK);

    const int dil[4]     = {1, 2, 4, 8};
    const int skipoff[4] = {184, 80, 8, 0};

    // ordered so launch index 3 (the profiled slot) is the layer-0 Y1 graph GEMM
    k_T<<<BB, 256>>>(p1, pk, ind, T1);                                   // 0
    k_adp<<<BB * NNODE, 256>>>(p2, p3, T1, adp);                         // 1
    k_gated0<<<BB * NNODE, 480>>>(inputs, start_w, start_b, S0, G,
        filt_w, filt_b, gate_w, gate_b, skip_w, skip_b, SK, skipoff[0]); // 2
    {
        int Ti = 15, L = 32 * Ti;
        dim3 grid((L + 127) / 128, (NNODE + 127) / 128, BB);
        k_gemm_tc<<<grid, 256>>>(adp, G, Y1, L, L, 0, L, 0);             // 3 <- profiled
        k_T<<<BB, 256>>>(a2p1, a2pk, ind, T2);                           // 4
        k_adp<<<BB * NNODE, 256>>>(a2p2, a2p3, T2, adp2);                // 5
        k_gemm_tc<<<grid, 256>>>(adp, Y1, Y2, L, L, 0, L, 0);
        k_g01<<<BB * NNODE, 32 * Ti>>>(G, Y1, Y2, gconv_w, gconv_b, G01, Ti);
        int L2 = 16 * Ti;
        dim3 grid2((L2 + 127) / 128, (NNODE + 127) / 128, BB);
        k_gemm_tc<<<grid2, 256>>>(adp2, G01, Z1, L2, 32 * Ti, 16 * Ti, L2, 0);
        k_gemm_tc<<<grid2, 256>>>(adp2, Z1, Z2, L2, L2, 0, L2, 0);
        k_update<<<BB * NNODE, 32 * Ti>>>(S0, G01, Z1, Z2, ga_w, ga_b, S1, 1, 16, Ti);
    }

    float* Sin = S1;
    float* Sout = S0;
    int Tin = 15;
    for (int i = 1; i < 4; i++) {
        int d = dil[i];
        int Ti = Tin - d;
        k_gated<<<BB * NNODE, 32 * Ti>>>(Sin, G,
            filt_w + i * 1024, filt_b + i * 32,
            gate_w + i * 1024, gate_b + i * 32,
            skip_w + i * 128, skip_b + i * 8, SK, skipoff[i], d, Tin, Ti);
        if (i < 3) {
            int L = 32 * Ti;
            dim3 grid((L + 127) / 128, (NNODE + 127) / 128, BB);
            k_gemm_tc<<<grid, 256>>>(adp, G,  Y1, L, L, 0, L, 0);
            k_gemm_tc<<<grid, 256>>>(adp, Y1, Y2, L, L, 0, L, 0);
            k_g01<<<BB * NNODE, 32 * Ti>>>(G, Y1, Y2,
                gconv_w + i * 1536, gconv_b + i * 32, G01, Ti);
            int L2 = 16 * Ti;
            dim3 grid2((L2 + 127) / 128, (NNODE + 127) / 128, BB);
            k_gemm_tc<<<grid2, 256>>>(adp2, G01, Z1, L2, 32 * Ti, 16 * Ti, L2, 0);
            k_gemm_tc<<<grid2, 256>>>(adp2, Z1,  Z2, L2, L2, 0, L2, 0);
            k_update<<<BB * NNODE, 32 * Ti>>>(Sin, G01, Z1, Z2,
                ga_w + i * 768, ga_b + i * 16, Sout, d, Tin, Ti);
            float* tmp = Sin; Sin = Sout; Sout = tmp;
        }
        Tin = Ti;
    }

    k_end<<<(BB * NNODE + 3) / 4, 128>>>(SK, end1_w, end1_b, end2_w, end2_b, out);
}